// round 1
// baseline (speedup 1.0000x reference)
#include <cuda_runtime.h>
#include <cstdint>

#define NN 100000
#define EE 400000
#define PP 250000
#define LL 16
#define DDIM 16
#define MTOT (PP * LL)
#define PPB 128   // p's per block

// -------- packed f32x2 helpers (Blackwell; only reachable via inline PTX) ----
#define FMAX2(acc, a, b) \
    asm("fma.rn.f32x2 %0, %1, %2, %0;" : "+l"(acc) : "l"(a), "l"(b))

__device__ int g_idx64;   // 1 if index arrays are int64, 0 if int32

// Detect index dtype from n_row (known to be arange(M)).
// int64 little-endian arange -> 32-bit words [0,0,1,0,...] -> w[1]==0
// int32 arange               -> [0,1,2,...]               -> w[1]==1
__global__ void detect_kernel(const int* __restrict__ nrow_words) {
    if (threadIdx.x == 0) g_idx64 = (nrow_words[1] == 0) ? 1 : 0;
}

// Main fused kernel: gather -> per-p 256x16 matvec -> relu(+bias) -> atomic pooled scatter
__global__ __launch_bounds__(128) void lrp_main_kernel(
    const float* __restrict__ nfeat,
    const void*  __restrict__ efeat_idx,
    const void*  __restrict__ n_col, const float* __restrict__ n_val,
    const void*  __restrict__ e_col, const float* __restrict__ e_val,
    const void*  __restrict__ p_row, const float* __restrict__ p_val,
    const float* __restrict__ weights, const float* __restrict__ bias,
    const float* __restrict__ bond_emb,
    float* __restrict__ out)
{
    extern __shared__ float smem[];
    float* sW    = smem;                   // 4096 : sW[(l*16+d)*16 + c]
    float* s_nv  = sW + 4096;              // 2048 : [l][p_local]
    float* s_ev  = s_nv + 2048;            // 2048
    int*   s_nc  = (int*)(s_ev + 2048);    // 2048 : packed nc | (t<<20)
    float* s_xs  = (float*)(s_nc + 2048);  // 2048 : xsT[q][row] float4
    float* sEmb  = s_xs + 2048;            // 64
    float* sBias = sEmb + 64;              // 16

    const int tid   = threadIdx.x;
    const int pbase = blockIdx.x * PPB;
    const bool i64  = (g_idx64 != 0);

    // ---- stage W transposed: sW[l*256 + d*16 + c] = weights[d*256 + c*16 + l]
    for (int i = tid; i < 4096; i += 128) {
        int l = i >> 8, d = (i >> 4) & 15, c = i & 15;
        sW[i] = weights[d * 256 + c * 16 + l];
    }
    if (tid < 64) sEmb[tid]  = bond_emb[tid];
    if (tid < 16) sBias[tid] = bias[tid];

    // ---- stage indices/vals for this block's 128 p's (coalesced global reads)
    #pragma unroll
    for (int i = tid; i < 2048; i += 128) {
        int pl = i >> 4, l = i & 15;
        int dst = l * 128 + pl;
        int m = (pbase + pl) * 16 + l;
        if (pbase + pl < PP) {
            long long ncl, ecl;
            if (i64) {
                ncl = ((const long long*)n_col)[m];
                ecl = ((const long long*)e_col)[m];
            } else {
                ncl = ((const int*)n_col)[m];
                ecl = ((const int*)e_col)[m];
            }
            int t = i64 ? (int)((const long long*)efeat_idx)[ecl]
                        : ((const int*)efeat_idx)[(int)ecl];
            s_nc[dst] = (int)ncl | (t << 20);
            s_nv[dst] = n_val[m];
            s_ev[dst] = e_val[m];
        } else {
            s_nc[dst] = 0; s_nv[dst] = 0.f; s_ev[dst] = 0.f;
        }
    }
    __syncthreads();

    unsigned long long yp[8];
    #pragma unroll
    for (int i = 0; i < 8; ++i) yp[i] = 0ull;

    float4* xsT4 = (float4*)s_xs;
    const float4* nf4 = (const float4*)nfeat;
    const float4* eb4 = (const float4*)sEmb;
    const ulonglong2* sW2 = (const ulonglong2*)sW;

    const int q  = tid & 3;   // quarter of row (d group)
    const int rb = tid >> 2;  // 0..31

    #pragma unroll 1
    for (int l = 0; l < 16; ++l) {
        // ---- cooperative x staging: 4 lanes per row, 32 rows/round, 4 rounds
        #pragma unroll
        for (int r0 = 0; r0 < 128; r0 += 32) {
            int row = r0 + rb;
            int v   = s_nc[l * 128 + row];
            float nv = s_nv[l * 128 + row];
            float ev = s_ev[l * 128 + row];
            int nc = v & 0xFFFFF;
            int t  = v >> 20;
            float4 nf = __ldg(&nf4[nc * 4 + q]);
            float4 eb = eb4[t * 4 + q];
            float4 x;
            x.x = nv * nf.x + ev * eb.x;
            x.y = nv * nf.y + ev * eb.y;
            x.z = nv * nf.z + ev * eb.z;
            x.w = nv * nf.w + ev * eb.w;
            xsT4[q * 128 + row] = x;
        }
        __syncthreads();

        // ---- compute: thread = p, accumulate y[c] over d via packed f32x2
        float4 xv[4];
        #pragma unroll
        for (int qq = 0; qq < 4; ++qq) xv[qq] = xsT4[qq * 128 + tid];

        #pragma unroll
        for (int j = 0; j < 4; ++j) {
            float ax0 = xv[j].x, ax1 = xv[j].y, ax2 = xv[j].z, ax3 = xv[j].w;
            #pragma unroll
            for (int dd = 0; dd < 4; ++dd) {
                float a = (dd == 0) ? ax0 : (dd == 1) ? ax1 : (dd == 2) ? ax2 : ax3;
                int k = l * 16 + j * 4 + dd;
                unsigned int au = __float_as_uint(a);
                unsigned long long aa;
                asm("mov.b64 %0, {%1, %1};" : "=l"(aa) : "r"(au));
                const ulonglong2* wp = sW2 + k * 4;   // 64B row of W, broadcast
                ulonglong2 wA = wp[0], wB = wp[1], wC = wp[2], wD = wp[3];
                FMAX2(yp[0], aa, wA.x); FMAX2(yp[1], aa, wA.y);
                FMAX2(yp[2], aa, wB.x); FMAX2(yp[3], aa, wB.y);
                FMAX2(yp[4], aa, wC.x); FMAX2(yp[5], aa, wC.y);
                FMAX2(yp[6], aa, wD.x); FMAX2(yp[7], aa, wD.y);
            }
        }
        __syncthreads();
    }

    // ---- epilogue: relu(y + bias), scatter p_val * y into out[p_row[p]]
    int p = pbase + tid;
    if (p < PP) {
        float yv[16];
        #pragma unroll
        for (int i = 0; i < 8; ++i) {
            unsigned int lo, hi;
            asm("mov.b64 {%0, %1}, %2;" : "=r"(lo), "=r"(hi) : "l"(yp[i]));
            yv[2 * i]     = __uint_as_float(lo);
            yv[2 * i + 1] = __uint_as_float(hi);
        }
        long long pr = i64 ? ((const long long*)p_row)[p]
                           : (long long)((const int*)p_row)[p];
        float pv = p_val[p];
        float* dst = out + pr * 16;
        #pragma unroll
        for (int c = 0; c < 16; ++c) {
            float v = fmaxf(yv[c] + sBias[c], 0.f);
            atomicAdd(dst + c, pv * v);
        }
    }
}

// Degree-gate MLP epilogue: out[n,c] *= (relu(degs[n]*W0 + b0) @ W1 + b1)[c]
__global__ void fd_kernel(const float* __restrict__ degs,
                          const float* __restrict__ W0, const float* __restrict__ b0,
                          const float* __restrict__ W1, const float* __restrict__ b1,
                          float* __restrict__ out)
{
    __shared__ float sw0[32], sb0[32], sw1[512], sb1[16];
    int tid = threadIdx.x;
    if (tid < 32) { sw0[tid] = W0[tid]; sb0[tid] = b0[tid]; }
    if (tid < 16) sb1[tid] = b1[tid];
    for (int i = tid; i < 512; i += blockDim.x) sw1[i] = W1[i];
    __syncthreads();

    int idx = blockIdx.x * blockDim.x + tid;
    if (idx >= NN * 16) return;
    int n = idx >> 4, c = idx & 15;
    float dg = degs[n];
    float fd = sb1[c];
    #pragma unroll
    for (int j = 0; j < 32; ++j) {
        float h = fmaxf(fmaf(dg, sw0[j], sb0[j]), 0.f);
        fd = fmaf(h, sw1[j * 16 + c], fd);
    }
    out[idx] *= fd;
}

extern "C" void kernel_launch(void* const* d_in, const int* in_sizes, int n_in,
                              void* d_out, int out_size)
{
    const float* nfeat     = (const float*)d_in[0];
    const void*  efeat_idx = d_in[1];
    const void*  n_row     = d_in[2];
    const void*  n_col     = d_in[3];
    const float* n_val     = (const float*)d_in[4];
    const void*  e_col     = d_in[6];
    const float* e_val     = (const float*)d_in[7];
    const void*  p_row     = d_in[8];
    const float* p_val     = (const float*)d_in[10];
    const float* degs      = (const float*)d_in[11];
    const float* weights   = (const float*)d_in[12];
    const float* bias      = (const float*)d_in[13];
    const float* W0        = (const float*)d_in[14];
    const float* b0        = (const float*)d_in[15];
    const float* W1        = (const float*)d_in[16];
    const float* b1        = (const float*)d_in[17];
    const float* bond_emb  = (const float*)d_in[18];
    float* out = (float*)d_out;

    const int smem_bytes = (4096 + 2048 * 4 + 64 + 16) * 4;  // 49,472 B
    cudaFuncSetAttribute(lrp_main_kernel,
                         cudaFuncAttributeMaxDynamicSharedMemorySize, smem_bytes);

    detect_kernel<<<1, 32>>>((const int*)n_row);
    cudaMemsetAsync(d_out, 0, (size_t)out_size * sizeof(float));

    int grid = (PP + PPB - 1) / PPB;  // 1954
    lrp_main_kernel<<<grid, 128, smem_bytes>>>(
        nfeat, efeat_idx, n_col, n_val, e_col, e_val,
        p_row, p_val, weights, bias, bond_emb, out);

    fd_kernel<<<(NN * 16 + 255) / 256, 256>>>(degs, W0, b0, W1, b1, out);
}

// round 2
// speedup vs baseline: 1.2269x; 1.2269x over previous
#include <cuda_runtime.h>
#include <cstdint>

#define NN 100000
#define EE 400000
#define PP 250000
#define PPB 128
#define NTHREADS 256

// Accumulation scratch: zero-initialized at load; fd_kernel re-zeros after reading,
// so every kernel_launch call sees it zeroed (deterministic, no memset node needed).
__device__ float g_scratch[NN * 16];

// Packed Blackwell f32x2 FMA (only reachable via inline PTX)
#define FMAX2(acc, a, b) \
    asm("fma.rn.f32x2 %0, %1, %2, %0;" : "+l"(acc) : "l"(a), "l"(b))

// Fused: gather -> per-p 256x16 matvec -> relu(+bias) -> atomic pooled scatter (into g_scratch)
__global__ __launch_bounds__(NTHREADS, 5) void lrp_main_kernel(
    const float* __restrict__ nfeat,
    const void*  __restrict__ efeat_idx,
    const void*  __restrict__ n_row_probe,
    const void*  __restrict__ n_col, const float* __restrict__ n_val,
    const void*  __restrict__ e_col, const float* __restrict__ e_val,
    const void*  __restrict__ p_row, const float* __restrict__ p_val,
    const float* __restrict__ weights, const float* __restrict__ bias,
    const float* __restrict__ bond_emb)
{
    __shared__ float sW[4096];     // sW[(l*16+d)*16 + c]
    __shared__ float s_nv[1024];   // [lsub][pl]
    __shared__ float s_ev[1024];
    __shared__ int   s_nc[1024];   // packed nc | (t<<20)
    __shared__ float s_xs[2048];   // x tile: [q][row] float4
    __shared__ float sEmb[64];
    __shared__ float sBias[16];

    const int tid   = threadIdx.x;
    const int pbase = blockIdx.x * PPB;
    // index dtype: n_row is arange(M); int64 -> second 32-bit word is 0
    const bool i64  = (((const int*)n_row_probe)[1] == 0);

    // ---- stage W transposed + emb + bias (once)
    #pragma unroll
    for (int i = tid; i < 4096; i += NTHREADS) {
        int l = i >> 8, d = (i >> 4) & 15, c = i & 15;
        sW[i] = weights[d * 256 + c * 16 + l];
    }
    if (tid < 64) sEmb[tid]  = bond_emb[tid];
    if (tid < 16) sBias[tid] = bias[tid];

    const int h  = tid >> 7;       // c-half: c in [8h, 8h+8)
    const int pt = tid & 127;      // p within block
    const int q  = tid & 3;        // d-quarter (staging)
    const int rbase = tid >> 2;    // 0..63  (staging row)

    unsigned long long yp[4];
    #pragma unroll
    for (int i = 0; i < 4; ++i) yp[i] = 0ull;

    const float4* nf4  = (const float4*)nfeat;
    const float4* eb4  = (const float4*)sEmb;
    float4*       xsT4 = (float4*)s_xs;

    #pragma unroll 1
    for (int ph = 0; ph < 2; ++ph) {
        // ---- stage indices/vals for l in [8ph, 8ph+8)  (sector-aligned coalesced)
        #pragma unroll
        for (int i = tid; i < 1024; i += NTHREADS) {
            int pl = i >> 3, lsub = i & 7;
            int dst = lsub * 128 + pl;
            int m = (pbase + pl) * 16 + 8 * ph + lsub;
            if (pbase + pl < PP) {
                long long ncl, ecl;
                if (i64) {
                    ncl = ((const long long*)n_col)[m];
                    ecl = ((const long long*)e_col)[m];
                } else {
                    ncl = ((const int*)n_col)[m];
                    ecl = ((const int*)e_col)[m];
                }
                int t = i64 ? (int)((const long long*)efeat_idx)[ecl]
                            : ((const int*)efeat_idx)[(int)ecl];
                s_nc[dst] = (int)ncl | (t << 20);
                s_nv[dst] = n_val[m];
                s_ev[dst] = e_val[m];
            } else {
                s_nc[dst] = 0; s_nv[dst] = 0.f; s_ev[dst] = 0.f;
            }
        }
        __syncthreads();

        #pragma unroll 1
        for (int lsub = 0; lsub < 8; ++lsub) {
            const int l = 8 * ph + lsub;

            // ---- cooperative x staging: 4 lanes per row, 64 rows/round, 2 rounds
            #pragma unroll
            for (int r0 = 0; r0 < 128; r0 += 64) {
                int row = r0 + rbase;
                int v    = s_nc[lsub * 128 + row];
                float nv = s_nv[lsub * 128 + row];
                float ev = s_ev[lsub * 128 + row];
                int nc = v & 0xFFFFF;
                int t  = v >> 20;
                float4 nf = __ldg(&nf4[nc * 4 + q]);
                float4 eb = eb4[t * 4 + q];
                float4 x;
                x.x = fmaf(nv, nf.x, ev * eb.x);
                x.y = fmaf(nv, nf.y, ev * eb.y);
                x.z = fmaf(nv, nf.z, ev * eb.z);
                x.w = fmaf(nv, nf.w, ev * eb.w);
                xsT4[q * 128 + row] = x;
            }
            __syncthreads();

            // ---- compute: thread (h,pt) accumulates y[8h..8h+8) over d for this l
            const ulonglong2* wrow = ((const ulonglong2*)sW) + l * 64 + 2 * h;
            #pragma unroll
            for (int j = 0; j < 4; ++j) {
                float4 xv = xsT4[j * 128 + pt];
                #pragma unroll
                for (int dd = 0; dd < 4; ++dd) {
                    float a = (dd == 0) ? xv.x : (dd == 1) ? xv.y : (dd == 2) ? xv.z : xv.w;
                    unsigned int au = __float_as_uint(a);
                    unsigned long long aa;
                    asm("mov.b64 %0, {%1, %1};" : "=l"(aa) : "r"(au));
                    const ulonglong2* wp = wrow + (j * 4 + dd) * 4;  // 32B of W (this c-half), broadcast
                    ulonglong2 wA = wp[0], wB = wp[1];
                    FMAX2(yp[0], aa, wA.x); FMAX2(yp[1], aa, wA.y);
                    FMAX2(yp[2], aa, wB.x); FMAX2(yp[3], aa, wB.y);
                }
            }
            __syncthreads();
        }
    }

    // ---- epilogue: relu(y + bias), scatter p_val * y into g_scratch[p_row[p], 8h..]
    int p = pbase + pt;
    if (p < PP) {
        float yv[8];
        #pragma unroll
        for (int i = 0; i < 4; ++i) {
            unsigned int lo, hi;
            asm("mov.b64 {%0, %1}, %2;" : "=r"(lo), "=r"(hi) : "l"(yp[i]));
            yv[2 * i]     = __uint_as_float(lo);
            yv[2 * i + 1] = __uint_as_float(hi);
        }
        long long pr = i64 ? ((const long long*)p_row)[p]
                           : (long long)((const int*)p_row)[p];
        float pv = p_val[p];
        float* dst = g_scratch + pr * 16 + 8 * h;
        #pragma unroll
        for (int c8 = 0; c8 < 8; ++c8) {
            float v = fmaxf(yv[c8] + sBias[8 * h + c8], 0.f);
            atomicAdd(dst + c8, pv * v);
        }
    }
}

// Degree-gate MLP: out[n,c] = scratch[n,c] * (relu(degs[n]*W0 + b0) @ W1 + b1)[c]
// Also re-zeros scratch for the next call.
__global__ void fd_kernel(const float* __restrict__ degs,
                          const float* __restrict__ W0, const float* __restrict__ b0,
                          const float* __restrict__ W1, const float* __restrict__ b1,
                          float* __restrict__ out)
{
    __shared__ float sw0[32], sb0[32], sw1[512], sb1[16];
    int tid = threadIdx.x;
    if (tid < 32) { sw0[tid] = W0[tid]; sb0[tid] = b0[tid]; }
    if (tid < 16) sb1[tid] = b1[tid];
    for (int i = tid; i < 512; i += blockDim.x) sw1[i] = W1[i];
    __syncthreads();

    int idx = blockIdx.x * blockDim.x + tid;
    if (idx >= NN * 16) return;
    int n = idx >> 4, c = idx & 15;
    float pooled = g_scratch[idx];
    g_scratch[idx] = 0.f;                 // restore invariant for next call
    float dg = degs[n];
    float fd = sb1[c];
    #pragma unroll
    for (int j = 0; j < 32; ++j) {
        float hdn = fmaxf(fmaf(dg, sw0[j], sb0[j]), 0.f);
        fd = fmaf(hdn, sw1[j * 16 + c], fd);
    }
    out[idx] = pooled * fd;
}

extern "C" void kernel_launch(void* const* d_in, const int* in_sizes, int n_in,
                              void* d_out, int out_size)
{
    const float* nfeat     = (const float*)d_in[0];
    const void*  efeat_idx = d_in[1];
    const void*  n_row     = d_in[2];
    const void*  n_col     = d_in[3];
    const float* n_val     = (const float*)d_in[4];
    const void*  e_col     = d_in[6];
    const float* e_val     = (const float*)d_in[7];
    const void*  p_row     = d_in[8];
    const float* p_val     = (const float*)d_in[10];
    const float* degs      = (const float*)d_in[11];
    const float* weights   = (const float*)d_in[12];
    const float* bias      = (const float*)d_in[13];
    const float* W0        = (const float*)d_in[14];
    const float* b0        = (const float*)d_in[15];
    const float* W1        = (const float*)d_in[16];
    const float* b1        = (const float*)d_in[17];
    const float* bond_emb  = (const float*)d_in[18];
    float* out = (float*)d_out;

    int grid = (PP + PPB - 1) / PPB;  // 1954
    lrp_main_kernel<<<grid, NTHREADS>>>(
        nfeat, efeat_idx, n_row, n_col, n_val, e_col, e_val,
        p_row, p_val, weights, bias, bond_emb);

    fd_kernel<<<(NN * 16 + 255) / 256, 256>>>(degs, W0, b0, W1, b1, out);
}

// round 4
// speedup vs baseline: 1.3371x; 1.0898x over previous
#include <cuda_runtime.h>
#include <cstdint>

#define NN 100000
#define EE 400000
#define PP 250000
#define PPB 256
#define NTHREADS 256

__device__ float g_fd[NN * 16];   // degree-gate values, recomputed every call

// Packed Blackwell f32x2 FMA (only reachable via inline PTX)
#define FMAX2(acc, a, b) \
    asm("fma.rn.f32x2 %0, %1, %2, %0;" : "+l"(acc) : "l"(a), "l"(b))
#define PACK2(dst, src) \
    asm("mov.b64 %0, {%1, %1};" : "=l"(dst) : "r"(src))

// ---------------------------------------------------------------------------
// Kernel 1: compute fd[n,c] = relu(degs[n]*W0 + b0) @ W1 + b1 into g_fd,
//           and zero d_out (so main kernel can atomically accumulate into it).
// ---------------------------------------------------------------------------
__global__ __launch_bounds__(256) void fd_pre_kernel(
    const float* __restrict__ degs,
    const float* __restrict__ W0, const float* __restrict__ b0,
    const float* __restrict__ W1, const float* __restrict__ b1,
    float* __restrict__ out)
{
    __shared__ float sw0[32], sb0[32];
    __shared__ ulonglong2 sw1v[128];   // W1 [32][16] floats, 16B-aligned
    __shared__ unsigned long long sb1p[8];

    int tid = threadIdx.x;
    if (tid < 32) { sw0[tid] = W0[tid]; sb0[tid] = b0[tid]; }
    if (tid < 128) sw1v[tid] = ((const ulonglong2*)W1)[tid];
    if (tid < 8)  sb1p[tid] = ((const unsigned long long*)b1)[tid];
    __syncthreads();

    int n = blockIdx.x * 256 + tid;
    if (n >= NN) return;

    unsigned long long acc[8];
    #pragma unroll
    for (int i = 0; i < 8; ++i) acc[i] = sb1p[i];

    float dg = degs[n];
    #pragma unroll
    for (int j = 0; j < 32; ++j) {
        float h = fmaxf(fmaf(dg, sw0[j], sb0[j]), 0.f);
        unsigned long long hh; PACK2(hh, __float_as_uint(h));
        const ulonglong2* wp = sw1v + j * 4;     // 16 floats for this j
        ulonglong2 wA = wp[0], wB = wp[1], wC = wp[2], wD = wp[3];
        FMAX2(acc[0], hh, wA.x); FMAX2(acc[1], hh, wA.y);
        FMAX2(acc[2], hh, wB.x); FMAX2(acc[3], hh, wB.y);
        FMAX2(acc[4], hh, wC.x); FMAX2(acc[5], hh, wC.y);
        FMAX2(acc[6], hh, wD.x); FMAX2(acc[7], hh, wD.y);
    }

    ulonglong2* fdv = (ulonglong2*)(g_fd + n * 16);
    fdv[0] = make_ulonglong2(acc[0], acc[1]);
    fdv[1] = make_ulonglong2(acc[2], acc[3]);
    fdv[2] = make_ulonglong2(acc[4], acc[5]);
    fdv[3] = make_ulonglong2(acc[6], acc[7]);

    float4 z = make_float4(0.f, 0.f, 0.f, 0.f);
    float4* ov = (float4*)(out + n * 16);
    ov[0] = z; ov[1] = z; ov[2] = z; ov[3] = z;
}

// ---------------------------------------------------------------------------
// Main kernel: gather -> per-p 256x16 matvec -> relu(+bias) -> *fd -> atomic
// scatter into out. Software-pipelined gather, 2 p's per thread.
// ---------------------------------------------------------------------------
__global__ __launch_bounds__(NTHREADS, 3) void lrp_main_kernel(
    const float* __restrict__ nfeat,
    const void*  __restrict__ efeat_idx,
    const void*  __restrict__ n_row_probe,
    const void*  __restrict__ n_col, const float* __restrict__ n_val,
    const void*  __restrict__ e_col, const float* __restrict__ e_val,
    const void*  __restrict__ p_row, const float* __restrict__ p_val,
    const float* __restrict__ weights, const float* __restrict__ bias,
    const float* __restrict__ bond_emb,
    float* __restrict__ out)
{
    extern __shared__ float smem[];
    float4* xs   = (float4*)smem;                 // 2 x 1024 float4 (x tiles)
    float*  sW   = smem + 8192;                   // 4096 : sW[k*16 + c]
    int*    s_nc = (int*)(sW + 4096);             // 2048 : [lsub][row]
    float*  s_nv = (float*)(s_nc + 2048);         // 2048
    float*  s_ev = s_nv + 2048;                   // 2048
    float*  sEmb = s_ev + 2048;                   // 64
    float*  sBias= sEmb + 64;                     // 16

    const int tid   = threadIdx.x;
    const int pbase = blockIdx.x * PPB;
    const bool i64  = (((const int*)n_row_probe)[1] == 0);

    // ---- stage W (transposed to [k=(l,d)][c]) + emb + bias
    #pragma unroll
    for (int i = tid; i < 4096; i += NTHREADS) {
        int l = i >> 8, d = (i >> 4) & 15, c = i & 15;
        sW[i] = weights[d * 256 + c * 16 + l];
    }
    if (tid < 64) sEmb[tid]  = bond_emb[tid];
    if (tid < 16) sBias[tid] = bias[tid];

    const int h  = tid >> 7;      // c-half
    const int pt = tid & 127;     // p slot (2 p's: pt, pt+128)
    const int q  = tid & 3;       // d-quarter (gather role)
    const int rb = tid >> 2;      // 0..63    (gather role)

    const float4* nf4 = (const float4*)nfeat;
    const float4* eb4 = (const float4*)sEmb;
    const ulonglong2* wll2 = (const ulonglong2*)sW;

    // ---- index staging for an 8-l chunk (pairs of l for coalescing)
    auto stage_idx = [&](int ph) {
        #pragma unroll
        for (int ii = 0; ii < 1024; ii += NTHREADS) {
            int i  = ii + tid;
            int pl = i >> 2, lp = i & 3;
            int lsub0 = 2 * lp;
            int d0 = lsub0 * 256 + pl;
            if (pbase + pl < PP) {
                int m0 = (pbase + pl) * 16 + ph * 8 + lsub0;   // even
                long long nc0, nc1, ec0, ec1;
                if (i64) {
                    longlong2 ncp = ((const longlong2*)n_col)[m0 >> 1];
                    longlong2 ecp = ((const longlong2*)e_col)[m0 >> 1];
                    nc0 = ncp.x; nc1 = ncp.y; ec0 = ecp.x; ec1 = ecp.y;
                } else {
                    int2 ncp = ((const int2*)n_col)[m0 >> 1];
                    int2 ecp = ((const int2*)e_col)[m0 >> 1];
                    nc0 = ncp.x; nc1 = ncp.y; ec0 = ecp.x; ec1 = ecp.y;
                }
                int t0 = i64 ? (int)((const long long*)efeat_idx)[ec0]
                             : ((const int*)efeat_idx)[(int)ec0];
                int t1 = i64 ? (int)((const long long*)efeat_idx)[ec1]
                             : ((const int*)efeat_idx)[(int)ec1];
                float2 nvp = ((const float2*)n_val)[m0 >> 1];
                float2 evp = ((const float2*)e_val)[m0 >> 1];
                s_nc[d0]       = (int)nc0 | (t0 << 20);
                s_nc[d0 + 256] = (int)nc1 | (t1 << 20);
                s_nv[d0]       = nvp.x;  s_nv[d0 + 256] = nvp.y;
                s_ev[d0]       = evp.x;  s_ev[d0 + 256] = evp.y;
            } else {
                s_nc[d0] = 0; s_nc[d0 + 256] = 0;
                s_nv[d0] = 0.f; s_nv[d0 + 256] = 0.f;
                s_ev[d0] = 0.f; s_ev[d0 + 256] = 0.f;
            }
        }
    };

    // gather-role registers (held across compute phase)
    float4 gnf[4]; float gnv[4], gev[4]; int gt[4];

    auto gather_issue = [&](int lsub) {
        #pragma unroll
        for (int r = 0; r < 4; ++r) {
            int row = rb + 64 * r;
            int v   = s_nc[lsub * 256 + row];
            gnv[r]  = s_nv[lsub * 256 + row];
            gev[r]  = s_ev[lsub * 256 + row];
            gt[r]   = v >> 20;
            gnf[r]  = __ldg(&nf4[(v & 0xFFFFF) * 4 + q]);
        }
    };
    auto gather_store = [&](int nbuf) {
        float4* xd = xs + nbuf * 1024;
        #pragma unroll
        for (int r = 0; r < 4; ++r) {
            int row = rb + 64 * r;
            float4 eb = eb4[gt[r] * 4 + q];
            float4 x;
            x.x = fmaf(gnv[r], gnf[r].x, gev[r] * eb.x);
            x.y = fmaf(gnv[r], gnf[r].y, gev[r] * eb.y);
            x.z = fmaf(gnv[r], gnf[r].z, gev[r] * eb.z);
            x.w = fmaf(gnv[r], gnf[r].w, gev[r] * eb.w);
            xd[q * 256 + row] = x;
        }
    };

    unsigned long long yp0[4], yp1[4];
    #pragma unroll
    for (int i = 0; i < 4; ++i) { yp0[i] = 0ull; yp1[i] = 0ull; }

    // ---- prologue: chunk 0 indices, first x tile
    stage_idx(0);
    __syncthreads();
    gather_issue(0);
    gather_store(0);
    __syncthreads();

    // ---- pipelined main loop
    #pragma unroll 1
    for (int l = 0; l < 16; ++l) {
        if (l == 8) {               // bring in idx chunk 1 (needed for gather l=8? no: l+1=9.. but also l=8's
            // gather was issued at l=7 from chunk1 -> stage earlier instead
        }
        if (l == 7) {
            stage_idx(1);
            __syncthreads();
        }
        if (l < 15) gather_issue((l + 1) & 7);   // next tile's scattered loads (latency hidden below)

        // compute l from buffer l&1
        const float4* xb = xs + (l & 1) * 1024;
        const ulonglong2* wbase = wll2 + l * 64 + h * 2;
        #pragma unroll
        for (int j = 0; j < 4; ++j) {
            float4 xv0 = xb[j * 256 + pt];
            float4 xv1 = xb[j * 256 + pt + 128];
            #pragma unroll
            for (int dd = 0; dd < 4; ++dd) {
                float a0 = (dd == 0) ? xv0.x : (dd == 1) ? xv0.y : (dd == 2) ? xv0.z : xv0.w;
                float a1 = (dd == 0) ? xv1.x : (dd == 1) ? xv1.y : (dd == 2) ? xv1.z : xv1.w;
                unsigned long long aa0, aa1;
                PACK2(aa0, __float_as_uint(a0));
                PACK2(aa1, __float_as_uint(a1));
                const ulonglong2* wp = wbase + (j * 4 + dd) * 4;
                ulonglong2 wA = wp[0], wB = wp[1];
                FMAX2(yp0[0], aa0, wA.x); FMAX2(yp0[1], aa0, wA.y);
                FMAX2(yp0[2], aa0, wB.x); FMAX2(yp0[3], aa0, wB.y);
                FMAX2(yp1[0], aa1, wA.x); FMAX2(yp1[1], aa1, wA.y);
                FMAX2(yp1[2], aa1, wB.x); FMAX2(yp1[3], aa1, wB.y);
            }
        }

        if (l < 15) {
            gather_store((l + 1) & 1);
            __syncthreads();
        }
    }

    // ---- epilogue: relu(y + bias) * pv * fd -> atomic scatter
    float bl[8];
    #pragma unroll
    for (int c8 = 0; c8 < 8; ++c8) bl[c8] = sBias[8 * h + c8];

    #pragma unroll
    for (int pp = 0; pp < 2; ++pp) {
        int p = pbase + 128 * pp + pt;
        if (p >= PP) continue;
        const unsigned long long* yp = pp ? yp1 : yp0;
        float yv[8];
        #pragma unroll
        for (int i = 0; i < 4; ++i) {
            unsigned int lo, hi;
            asm("mov.b64 {%0, %1}, %2;" : "=r"(lo), "=r"(hi) : "l"(yp[i]));
            yv[2 * i]     = __uint_as_float(lo);
            yv[2 * i + 1] = __uint_as_float(hi);
        }
        long long pr = i64 ? ((const long long*)p_row)[p]
                           : (long long)((const int*)p_row)[p];
        float pv = p_val[p];
        const float4 f0 = __ldg((const float4*)(g_fd + pr * 16 + 8 * h));
        const float4 f1 = __ldg((const float4*)(g_fd + pr * 16 + 8 * h + 4));
        float fdv[8] = {f0.x, f0.y, f0.z, f0.w, f1.x, f1.y, f1.z, f1.w};
        float* dst = out + pr * 16 + 8 * h;
        #pragma unroll
        for (int c8 = 0; c8 < 8; ++c8) {
            float v = fmaxf(yv[c8] + bl[c8], 0.f);
            atomicAdd(dst + c8, pv * v * fdv[c8]);
        }
    }
}

extern "C" void kernel_launch(void* const* d_in, const int* in_sizes, int n_in,
                              void* d_out, int out_size)
{
    const float* nfeat     = (const float*)d_in[0];
    const void*  efeat_idx = d_in[1];
    const void*  n_row     = d_in[2];
    const void*  n_col     = d_in[3];
    const float* n_val     = (const float*)d_in[4];
    const void*  e_col     = d_in[6];
    const float* e_val     = (const float*)d_in[7];
    const void*  p_row     = d_in[8];
    const float* p_val     = (const float*)d_in[10];
    const float* degs      = (const float*)d_in[11];
    const float* weights   = (const float*)d_in[12];
    const float* bias      = (const float*)d_in[13];
    const float* W0        = (const float*)d_in[14];
    const float* b0        = (const float*)d_in[15];
    const float* W1        = (const float*)d_in[16];
    const float* b1        = (const float*)d_in[17];
    const float* bond_emb  = (const float*)d_in[18];
    float* out = (float*)d_out;

    // fd (+ output zeroing) first; main kernel LAST so ncu -s 5 -c 1 captures it
    fd_pre_kernel<<<(NN + 255) / 256, 256>>>(degs, W0, b0, W1, b1, out);

    const int smem_bytes = (8192 * 4) + (4096 * 4) + (2048 * 4 * 3) + (64 + 16) * 4;  // 74048
    cudaFuncSetAttribute(lrp_main_kernel,
                         cudaFuncAttributeMaxDynamicSharedMemorySize, smem_bytes);
    int grid = (PP + PPB - 1) / PPB;  // 977
    lrp_main_kernel<<<grid, NTHREADS, smem_bytes>>>(
        nfeat, efeat_idx, n_row, n_col, n_val, e_col, e_val,
        p_row, p_val, weights, bias, bond_emb, out);
}

// round 5
// speedup vs baseline: 1.6481x; 1.2326x over previous
#include <cuda_runtime.h>
#include <cstdint>

#define NN 100000
#define PP 250000
#define PPB 256
#define NTHREADS 256

__device__ float g_fd[NN * 16];   // degree-gate values, recomputed every call

// Packed Blackwell f32x2 ops (only reachable via inline PTX)
#define FMAX2(acc, a, b) \
    asm("fma.rn.f32x2 %0, %1, %2, %0;" : "+l"(acc) : "l"(a), "l"(b))
#define PACK2(dst, src) \
    asm("mov.b64 %0, {%1, %1};" : "=l"(dst) : "r"(src))
#define RED4(ptr, a, b, c, d) \
    asm volatile("red.global.add.v4.f32 [%0], {%1,%2,%3,%4};" \
                 :: "l"(ptr), "f"(a), "f"(b), "f"(c), "f"(d) : "memory")

// ---------------------------------------------------------------------------
// Kernel 1: fd[n,c] = relu(degs[n]*W0 + b0) @ W1 + b1 into g_fd; zero d_out.
// ---------------------------------------------------------------------------
__global__ __launch_bounds__(256) void fd_pre_kernel(
    const float* __restrict__ degs,
    const float* __restrict__ W0, const float* __restrict__ b0,
    const float* __restrict__ W1, const float* __restrict__ b1,
    float* __restrict__ out)
{
    __shared__ float sw0[32], sb0[32];
    __shared__ ulonglong2 sw1v[128];
    __shared__ unsigned long long sb1p[8];

    int tid = threadIdx.x;
    if (tid < 32) { sw0[tid] = W0[tid]; sb0[tid] = b0[tid]; }
    if (tid < 128) sw1v[tid] = ((const ulonglong2*)W1)[tid];
    if (tid < 8)  sb1p[tid] = ((const unsigned long long*)b1)[tid];
    __syncthreads();

    int n = blockIdx.x * 256 + tid;
    if (n >= NN) return;

    unsigned long long acc[8];
    #pragma unroll
    for (int i = 0; i < 8; ++i) acc[i] = sb1p[i];

    float dg = degs[n];
    #pragma unroll
    for (int j = 0; j < 32; ++j) {
        float h = fmaxf(fmaf(dg, sw0[j], sb0[j]), 0.f);
        unsigned long long hh; PACK2(hh, __float_as_uint(h));
        const ulonglong2* wp = sw1v + j * 4;
        ulonglong2 wA = wp[0], wB = wp[1], wC = wp[2], wD = wp[3];
        FMAX2(acc[0], hh, wA.x); FMAX2(acc[1], hh, wA.y);
        FMAX2(acc[2], hh, wB.x); FMAX2(acc[3], hh, wB.y);
        FMAX2(acc[4], hh, wC.x); FMAX2(acc[5], hh, wC.y);
        FMAX2(acc[6], hh, wD.x); FMAX2(acc[7], hh, wD.y);
    }

    ulonglong2* fdv = (ulonglong2*)(g_fd + n * 16);
    fdv[0] = make_ulonglong2(acc[0], acc[1]);
    fdv[1] = make_ulonglong2(acc[2], acc[3]);
    fdv[2] = make_ulonglong2(acc[4], acc[5]);
    fdv[3] = make_ulonglong2(acc[6], acc[7]);

    float4 z = make_float4(0.f, 0.f, 0.f, 0.f);
    float4* ov = (float4*)(out + n * 16);
    ov[0] = z; ov[1] = z; ov[2] = z; ov[3] = z;
}

// ---------------------------------------------------------------------------
// Main kernel: registers-only x path with quad shuffles.
// Thread (q = tid&3, rb = tid>>2): gathers quarter q of rows rb+64r (r=0..3),
// accumulates y[rows, c-quarter q] via shfl-broadcast x + conflict-free W LDS.
// ---------------------------------------------------------------------------
__global__ __launch_bounds__(NTHREADS, 3) void lrp_main_kernel(
    const float* __restrict__ nfeat,
    const void*  __restrict__ efeat_idx,
    const void*  __restrict__ n_row_probe,
    const void*  __restrict__ n_col, const float* __restrict__ n_val,
    const void*  __restrict__ e_col, const float* __restrict__ e_val,
    const void*  __restrict__ p_row, const float* __restrict__ p_val,
    const float* __restrict__ weights, const float* __restrict__ bias,
    const float* __restrict__ bond_emb,
    float* __restrict__ out)
{
    extern __shared__ float smem[];
    float* sW    = smem;                    // 4096  : sW[k*16 + c], k=(l,d)
    int*   s_nc  = (int*)(sW + 4096);       // 4096  : [l][row] packed nc|t<<20
    float* s_nv  = (float*)(s_nc + 4096);   // 4096
    float* s_ev  = s_nv + 4096;             // 4096
    float* sEmb  = s_ev + 4096;             // 64
    float* sBias = sEmb + 64;               // 16

    const int tid   = threadIdx.x;
    const int pbase = blockIdx.x * PPB;
    const bool i64  = (((const int*)n_row_probe)[1] == 0);

    // ---- stage W transposed + emb + bias
    #pragma unroll
    for (int i = tid; i < 4096; i += NTHREADS) {
        int l = i >> 8, d = (i >> 4) & 15, c = i & 15;
        sW[i] = weights[d * 256 + c * 16 + l];
    }
    if (tid < 64) sEmb[tid]  = bond_emb[tid];
    if (tid < 16) sBias[tid] = bias[tid];

    // ---- stage ALL 4096 m-rows for this block (pairs, coalesced)
    const long long mhalf = (long long)pbase * 8;   // (pbase*16)/2
    #pragma unroll 1
    for (int it = 0; it < 8; ++it) {
        int i  = it * NTHREADS + tid;   // pair idx 0..2047
        int m0 = i << 1;                // local m (even)
        int pl = m0 >> 4;
        int l  = m0 & 15;
        int d0 = l * 256 + pl;
        if (pbase + pl < PP) {
            long long nc0, nc1, ec0, ec1;
            if (i64) {
                longlong2 ncp = ((const longlong2*)n_col)[mhalf + i];
                longlong2 ecp = ((const longlong2*)e_col)[mhalf + i];
                nc0 = ncp.x; nc1 = ncp.y; ec0 = ecp.x; ec1 = ecp.y;
            } else {
                int2 ncp = ((const int2*)n_col)[mhalf + i];
                int2 ecp = ((const int2*)e_col)[mhalf + i];
                nc0 = ncp.x; nc1 = ncp.y; ec0 = ecp.x; ec1 = ecp.y;
            }
            int t0 = i64 ? (int)((const long long*)efeat_idx)[ec0]
                         : ((const int*)efeat_idx)[(int)ec0];
            int t1 = i64 ? (int)((const long long*)efeat_idx)[ec1]
                         : ((const int*)efeat_idx)[(int)ec1];
            float2 nvp = ((const float2*)n_val)[mhalf + i];
            float2 evp = ((const float2*)e_val)[mhalf + i];
            s_nc[d0]       = (int)nc0 | (t0 << 20);
            s_nc[d0 + 256] = (int)nc1 | (t1 << 20);
            s_nv[d0]       = nvp.x;  s_nv[d0 + 256] = nvp.y;
            s_ev[d0]       = evp.x;  s_ev[d0 + 256] = evp.y;
        } else {
            s_nc[d0] = 0;  s_nc[d0 + 256] = 0;
            s_nv[d0] = 0.f; s_nv[d0 + 256] = 0.f;
            s_ev[d0] = 0.f; s_ev[d0 + 256] = 0.f;
        }
    }
    __syncthreads();    // the only block-wide barrier

    const int q    = tid & 3;
    const int rb   = tid >> 2;           // 0..63
    const int lane = tid & 31;
    const int qsrc = lane & ~3;          // quad base lane

    const float4* nf4 = (const float4*)nfeat;
    const float4* eb4 = (const float4*)sEmb;
    const ulonglong2* sW2 = (const ulonglong2*)sW;

    unsigned long long acc[4][2];
    #pragma unroll
    for (int r = 0; r < 4; ++r) { acc[r][0] = 0ull; acc[r][1] = 0ull; }

    float4 gnf[4]; int gt[4];

    // issue gathers for l = 0
    #pragma unroll
    for (int r = 0; r < 4; ++r) {
        int v = s_nc[rb + 64 * r];
        gt[r]  = v >> 20;
        gnf[r] = __ldg(&nf4[(v & 0xFFFFF) * 4 + q]);
    }

    #pragma unroll 1
    for (int l = 0; l < 16; ++l) {
        // ---- convert: xr[r] = nv*nfeat + ev*emb (quarter q of row rb+64r)
        float4 xr[4];
        #pragma unroll
        for (int r = 0; r < 4; ++r) {
            int row = l * 256 + rb + 64 * r;
            float nv = s_nv[row], ev = s_ev[row];
            float4 eb = eb4[gt[r] * 4 + q];
            xr[r].x = fmaf(nv, gnf[r].x, ev * eb.x);
            xr[r].y = fmaf(nv, gnf[r].y, ev * eb.y);
            xr[r].z = fmaf(nv, gnf[r].z, ev * eb.z);
            xr[r].w = fmaf(nv, gnf[r].w, ev * eb.w);
        }
        // ---- issue next l's gathers (latency hidden under compute below)
        if (l < 15) {
            #pragma unroll
            for (int r = 0; r < 4; ++r) {
                int v = s_nc[(l + 1) * 256 + rb + 64 * r];
                gt[r]  = v >> 20;
                gnf[r] = __ldg(&nf4[(v & 0xFFFFF) * 4 + q]);
            }
        }
        // ---- compute: quad-broadcast x, shared conflict-free W reads
        #pragma unroll
        for (int dq = 0; dq < 4; ++dq) {
            #pragma unroll
            for (int dd = 0; dd < 4; ++dd) {
                int k = l * 16 + dq * 4 + dd;
                ulonglong2 w = sW2[k * 4 + q];   // lanes read 64B contiguous: 1 wavefront
                #pragma unroll
                for (int r = 0; r < 4; ++r) {
                    float comp = (dd == 0) ? xr[r].x : (dd == 1) ? xr[r].y
                               : (dd == 2) ? xr[r].z : xr[r].w;
                    float a = __shfl_sync(0xffffffffu, comp, qsrc + dq, 32);
                    unsigned long long aa; PACK2(aa, __float_as_uint(a));
                    FMAX2(acc[r][0], aa, w.x);
                    FMAX2(acc[r][1], aa, w.y);
                }
            }
        }
    }

    // ---- epilogue: relu(y + bias) * pv * fd -> vector red into out
    float b0 = sBias[4 * q + 0], b1 = sBias[4 * q + 1];
    float b2 = sBias[4 * q + 2], b3 = sBias[4 * q + 3];
    #pragma unroll
    for (int r = 0; r < 4; ++r) {
        int p = pbase + rb + 64 * r;
        if (p >= PP) continue;
        long long pr = i64 ? ((const long long*)p_row)[p]
                           : (long long)((const int*)p_row)[p];
        float pv = p_val[p];
        float4 fd = __ldg((const float4*)(g_fd + pr * 16 + 4 * q));
        unsigned int lo, hi;
        float y0, y1, y2, y3;
        asm("mov.b64 {%0, %1}, %2;" : "=r"(lo), "=r"(hi) : "l"(acc[r][0]));
        y0 = __uint_as_float(lo); y1 = __uint_as_float(hi);
        asm("mov.b64 {%0, %1}, %2;" : "=r"(lo), "=r"(hi) : "l"(acc[r][1]));
        y2 = __uint_as_float(lo); y3 = __uint_as_float(hi);
        float v0 = fmaxf(y0 + b0, 0.f) * pv * fd.x;
        float v1 = fmaxf(y1 + b1, 0.f) * pv * fd.y;
        float v2 = fmaxf(y2 + b2, 0.f) * pv * fd.z;
        float v3 = fmaxf(y3 + b3, 0.f) * pv * fd.w;
        const float* dst = out + pr * 16 + 4 * q;
        RED4(dst, v0, v1, v2, v3);
    }
}

extern "C" void kernel_launch(void* const* d_in, const int* in_sizes, int n_in,
                              void* d_out, int out_size)
{
    const float* nfeat     = (const float*)d_in[0];
    const void*  efeat_idx = d_in[1];
    const void*  n_row     = d_in[2];
    const void*  n_col     = d_in[3];
    const float* n_val     = (const float*)d_in[4];
    const void*  e_col     = d_in[6];
    const float* e_val     = (const float*)d_in[7];
    const void*  p_row     = d_in[8];
    const float* p_val     = (const float*)d_in[10];
    const float* degs      = (const float*)d_in[11];
    const float* weights   = (const float*)d_in[12];
    const float* bias      = (const float*)d_in[13];
    const float* W0        = (const float*)d_in[14];
    const float* b0        = (const float*)d_in[15];
    const float* W1        = (const float*)d_in[16];
    const float* b1        = (const float*)d_in[17];
    const float* bond_emb  = (const float*)d_in[18];
    float* out = (float*)d_out;

    // fd (+ output zeroing) first; main kernel LAST so ncu -s 5 -c 1 captures it
    fd_pre_kernel<<<(NN + 255) / 256, 256>>>(degs, W0, b0, W1, b1, out);

    const int smem_bytes = (4096 * 4 + 64 + 16) * sizeof(float);  // 65,856 B
    cudaFuncSetAttribute(lrp_main_kernel,
                         cudaFuncAttributeMaxDynamicSharedMemorySize, smem_bytes);
    int grid = (PP + PPB - 1) / PPB;  // 977
    lrp_main_kernel<<<grid, NTHREADS, smem_bytes>>>(
        nfeat, efeat_idx, n_row, n_col, n_val, e_col, e_val,
        p_row, p_val, weights, bias, bond_emb, out);
}

// round 6
// speedup vs baseline: 1.7133x; 1.0395x over previous
#include <cuda_runtime.h>
#include <cstdint>

#define NN 100000
#define PP 250000
#define PPB 128
#define NTHREADS 256

__device__ float g_fd[NN * 16];   // degree-gate values, recomputed every call

// Packed Blackwell f32x2 ops (only reachable via inline PTX)
#define FMAX2(acc, a, b) \
    asm("fma.rn.f32x2 %0, %1, %2, %0;" : "+l"(acc) : "l"(a), "l"(b))
#define ADD2(acc, b) \
    asm("add.rn.f32x2 %0, %0, %1;" : "+l"(acc) : "l"(b))
#define PACK2(dst, src) \
    asm("mov.b64 %0, {%1, %1};" : "=l"(dst) : "r"(src))
#define RED4(ptr, a, b, c, d) \
    asm volatile("red.global.add.v4.f32 [%0], {%1,%2,%3,%4};" \
                 :: "l"(ptr), "f"(a), "f"(b), "f"(c), "f"(d) : "memory")

// ---------------------------------------------------------------------------
// Kernel 1: fd[n,c] = relu(degs[n]*W0 + b0) @ W1 + b1 into g_fd; zero d_out.
// ---------------------------------------------------------------------------
__global__ __launch_bounds__(256) void fd_pre_kernel(
    const float* __restrict__ degs,
    const float* __restrict__ W0, const float* __restrict__ b0,
    const float* __restrict__ W1, const float* __restrict__ b1,
    float* __restrict__ out)
{
    __shared__ float sw0[32], sb0[32];
    __shared__ ulonglong2 sw1v[128];
    __shared__ unsigned long long sb1p[8];

    int tid = threadIdx.x;
    if (tid < 32) { sw0[tid] = W0[tid]; sb0[tid] = b0[tid]; }
    if (tid < 128) sw1v[tid] = ((const ulonglong2*)W1)[tid];
    if (tid < 8)  sb1p[tid] = ((const unsigned long long*)b1)[tid];
    __syncthreads();

    int n = blockIdx.x * 256 + tid;
    if (n >= NN) return;

    unsigned long long acc[8];
    #pragma unroll
    for (int i = 0; i < 8; ++i) acc[i] = sb1p[i];

    float dg = degs[n];
    #pragma unroll
    for (int j = 0; j < 32; ++j) {
        float h = fmaxf(fmaf(dg, sw0[j], sb0[j]), 0.f);
        unsigned long long hh; PACK2(hh, __float_as_uint(h));
        const ulonglong2* wp = sw1v + j * 4;
        ulonglong2 wA = wp[0], wB = wp[1], wC = wp[2], wD = wp[3];
        FMAX2(acc[0], hh, wA.x); FMAX2(acc[1], hh, wA.y);
        FMAX2(acc[2], hh, wB.x); FMAX2(acc[3], hh, wB.y);
        FMAX2(acc[4], hh, wC.x); FMAX2(acc[5], hh, wC.y);
        FMAX2(acc[6], hh, wD.x); FMAX2(acc[7], hh, wD.y);
    }

    ulonglong2* fdv = (ulonglong2*)(g_fd + n * 16);
    fdv[0] = make_ulonglong2(acc[0], acc[1]);
    fdv[1] = make_ulonglong2(acc[2], acc[3]);
    fdv[2] = make_ulonglong2(acc[4], acc[5]);
    fdv[3] = make_ulonglong2(acc[6], acc[7]);

    float4 z = make_float4(0.f, 0.f, 0.f, 0.f);
    float4* ov = (float4*)(out + n * 16);
    ov[0] = z; ov[1] = z; ov[2] = z; ov[3] = z;
}

// ---------------------------------------------------------------------------
// Main kernel, shuffle-free compute:
// thread (q = tid&3, rb = tid>>2) owns x[d in 4q..4q+4) of rows {rb, rb+64}
// and accumulates PARTIAL y over all 16 c for its d-quarter. One quad
// butterfly (2 rounds) at the end produces the full y; lane q writes its
// c-quarter via red.global.add.v4.f32.
// W is stored swizzled: 16B chunk cc of row k lives at slot (cc ^ ((k>>2)&3))
// so a quad's 4 lanes (k strided by 4) hit 4 distinct banks: conflict-free.
// ---------------------------------------------------------------------------
__global__ __launch_bounds__(NTHREADS, 3) void lrp_main_kernel(
    const float* __restrict__ nfeat,
    const void*  __restrict__ efeat_idx,
    const void*  __restrict__ n_row_probe,
    const void*  __restrict__ n_col, const float* __restrict__ n_val,
    const void*  __restrict__ e_col, const float* __restrict__ e_val,
    const void*  __restrict__ p_row, const float* __restrict__ p_val,
    const float* __restrict__ weights, const float* __restrict__ bias,
    const float* __restrict__ bond_emb,
    float* __restrict__ out)
{
    extern __shared__ float smem[];
    float* sW    = smem;                    // 4096 : swizzled [k][cc^..][c&3]
    int*   s_nc  = (int*)(sW + 4096);       // 2048 : [l][row] packed nc|t<<20
    float* s_nv  = (float*)(s_nc + 2048);   // 2048
    float* s_ev  = s_nv + 2048;             // 2048
    float* sEmb  = s_ev + 2048;             // 64
    float* sBias = sEmb + 64;               // 16

    const int tid   = threadIdx.x;
    const int pbase = blockIdx.x * PPB;
    const bool i64  = (((const int*)n_row_probe)[1] == 0);

    // ---- stage W transposed + swizzled
    #pragma unroll
    for (int i = tid; i < 4096; i += NTHREADS) {
        int k = i >> 4, c = i & 15;
        int l = k >> 4, d = k & 15;
        int cc = (c >> 2) ^ ((k >> 2) & 3);
        sW[k * 16 + (cc << 2) + (c & 3)] = weights[d * 256 + c * 16 + l];
    }
    if (tid < 64) sEmb[tid]  = bond_emb[tid];
    if (tid < 16) sBias[tid] = bias[tid];

    // ---- stage 2048 m-rows for this block (pairs, coalesced)
    const long long mhalf = (long long)pbase * 8;
    #pragma unroll 1
    for (int it = 0; it < 4; ++it) {
        int i  = it * NTHREADS + tid;   // pair idx 0..1023
        int m0 = i << 1;
        int pl = m0 >> 4;
        int l  = m0 & 15;
        int d0 = l * 128 + pl;
        if (pbase + pl < PP) {
            long long nc0, nc1, ec0, ec1;
            if (i64) {
                longlong2 ncp = ((const longlong2*)n_col)[mhalf + i];
                longlong2 ecp = ((const longlong2*)e_col)[mhalf + i];
                nc0 = ncp.x; nc1 = ncp.y; ec0 = ecp.x; ec1 = ecp.y;
            } else {
                int2 ncp = ((const int2*)n_col)[mhalf + i];
                int2 ecp = ((const int2*)e_col)[mhalf + i];
                nc0 = ncp.x; nc1 = ncp.y; ec0 = ecp.x; ec1 = ecp.y;
            }
            int t0 = i64 ? (int)((const long long*)efeat_idx)[ec0]
                         : ((const int*)efeat_idx)[(int)ec0];
            int t1 = i64 ? (int)((const long long*)efeat_idx)[ec1]
                         : ((const int*)efeat_idx)[(int)ec1];
            float2 nvp = ((const float2*)n_val)[mhalf + i];
            float2 evp = ((const float2*)e_val)[mhalf + i];
            s_nc[d0]       = (int)nc0 | (t0 << 20);
            s_nc[d0 + 128] = (int)nc1 | (t1 << 20);
            s_nv[d0]       = nvp.x;  s_nv[d0 + 128] = nvp.y;
            s_ev[d0]       = evp.x;  s_ev[d0 + 128] = evp.y;
        } else {
            s_nc[d0] = 0;  s_nc[d0 + 128] = 0;
            s_nv[d0] = 0.f; s_nv[d0 + 128] = 0.f;
            s_ev[d0] = 0.f; s_ev[d0 + 128] = 0.f;
        }
    }
    __syncthreads();    // the only block-wide barrier

    const int q  = tid & 3;
    const int rb = tid >> 2;           // 0..63

    const float4* nf4 = (const float4*)nfeat;
    const float4* eb4 = (const float4*)sEmb;
    const ulonglong2* sW2 = (const ulonglong2*)sW;

    // acc[r][j]: partial y (this d-quarter) of row rb+64r, c = 2j, 2j+1
    unsigned long long acc[2][8];
    #pragma unroll
    for (int r = 0; r < 2; ++r)
        #pragma unroll
        for (int j = 0; j < 8; ++j) acc[r][j] = 0ull;

    float4 gnf[2]; int gt[2];
    #pragma unroll
    for (int r = 0; r < 2; ++r) {
        int v = s_nc[rb + 64 * r];
        gt[r]  = v >> 20;
        gnf[r] = __ldg(&nf4[(v & 0xFFFFF) * 4 + q]);
    }

    #pragma unroll 1
    for (int l = 0; l < 16; ++l) {
        // ---- convert to x (this thread's d-quarter, 2 rows)
        float4 xr[2];
        #pragma unroll
        for (int r = 0; r < 2; ++r) {
            int row = l * 128 + rb + 64 * r;
            float nv = s_nv[row], ev = s_ev[row];
            float4 eb = eb4[gt[r] * 4 + q];
            xr[r].x = fmaf(nv, gnf[r].x, ev * eb.x);
            xr[r].y = fmaf(nv, gnf[r].y, ev * eb.y);
            xr[r].z = fmaf(nv, gnf[r].z, ev * eb.z);
            xr[r].w = fmaf(nv, gnf[r].w, ev * eb.w);
        }
        // ---- issue next l's gathers (latency hidden under compute)
        if (l < 15) {
            #pragma unroll
            for (int r = 0; r < 2; ++r) {
                int v = s_nc[(l + 1) * 128 + rb + 64 * r];
                gt[r]  = v >> 20;
                gnf[r] = __ldg(&nf4[(v & 0xFFFFF) * 4 + q]);
            }
        }
        // ---- accumulate: own-x, swizzled conflict-free W
        #pragma unroll
        for (int dd = 0; dd < 4; ++dd) {
            const int k = l * 16 + q * 4 + dd;
            unsigned long long a0, a1;
            {
                float c0 = (dd == 0) ? xr[0].x : (dd == 1) ? xr[0].y
                         : (dd == 2) ? xr[0].z : xr[0].w;
                float c1 = (dd == 0) ? xr[1].x : (dd == 1) ? xr[1].y
                         : (dd == 2) ? xr[1].z : xr[1].w;
                PACK2(a0, __float_as_uint(c0));
                PACK2(a1, __float_as_uint(c1));
            }
            #pragma unroll
            for (int cc = 0; cc < 4; ++cc) {
                ulonglong2 w = sW2[k * 4 + (cc ^ q)];   // 4 distinct banks in quad
                FMAX2(acc[0][2 * cc],     a0, w.x);
                FMAX2(acc[0][2 * cc + 1], a0, w.y);
                FMAX2(acc[1][2 * cc],     a1, w.x);
                FMAX2(acc[1][2 * cc + 1], a1, w.y);
            }
        }
    }

    // ---- quad butterfly reduction over d-quarters (all lanes get full y)
    #pragma unroll
    for (int m = 1; m <= 2; m <<= 1) {
        #pragma unroll
        for (int r = 0; r < 2; ++r)
            #pragma unroll
            for (int j = 0; j < 8; ++j) {
                unsigned long long o =
                    __shfl_xor_sync(0xffffffffu, acc[r][j], m, 32);
                ADD2(acc[r][j], o);
            }
    }

    // ---- epilogue: lane q writes c-quarter q of its 2 rows
    float b0 = sBias[4 * q + 0], b1 = sBias[4 * q + 1];
    float b2 = sBias[4 * q + 2], b3 = sBias[4 * q + 3];
    #pragma unroll
    for (int r = 0; r < 2; ++r) {
        int p = pbase + rb + 64 * r;
        if (p >= PP) continue;
        long long pr = i64 ? ((const long long*)p_row)[p]
                           : (long long)((const int*)p_row)[p];
        float pv = p_val[p];
        float4 fd = __ldg((const float4*)(g_fd + pr * 16 + 4 * q));
        unsigned int lo, hi;
        float y0, y1, y2, y3;
        asm("mov.b64 {%0, %1}, %2;" : "=r"(lo), "=r"(hi) : "l"(acc[r][2 * q]));
        y0 = __uint_as_float(lo); y1 = __uint_as_float(hi);
        asm("mov.b64 {%0, %1}, %2;" : "=r"(lo), "=r"(hi) : "l"(acc[r][2 * q + 1]));
        y2 = __uint_as_float(lo); y3 = __uint_as_float(hi);
        float v0 = fmaxf(y0 + b0, 0.f) * pv * fd.x;
        float v1 = fmaxf(y1 + b1, 0.f) * pv * fd.y;
        float v2 = fmaxf(y2 + b2, 0.f) * pv * fd.z;
        float v3 = fmaxf(y3 + b3, 0.f) * pv * fd.w;
        const float* dst = out + pr * 16 + 4 * q;
        RED4(dst, v0, v1, v2, v3);
    }
}

extern "C" void kernel_launch(void* const* d_in, const int* in_sizes, int n_in,
                              void* d_out, int out_size)
{
    const float* nfeat     = (const float*)d_in[0];
    const void*  efeat_idx = d_in[1];
    const void*  n_row     = d_in[2];
    const void*  n_col     = d_in[3];
    const float* n_val     = (const float*)d_in[4];
    const void*  e_col     = d_in[6];
    const float* e_val     = (const float*)d_in[7];
    const void*  p_row     = d_in[8];
    const float* p_val     = (const float*)d_in[10];
    const float* degs      = (const float*)d_in[11];
    const float* weights   = (const float*)d_in[12];
    const float* bias      = (const float*)d_in[13];
    const float* W0        = (const float*)d_in[14];
    const float* b0        = (const float*)d_in[15];
    const float* W1        = (const float*)d_in[16];
    const float* b1        = (const float*)d_in[17];
    const float* bond_emb  = (const float*)d_in[18];
    float* out = (float*)d_out;

    // fd (+ output zeroing) first; main kernel LAST so ncu -s 5 -c 1 captures it
    fd_pre_kernel<<<(NN + 255) / 256, 256>>>(degs, W0, b0, W1, b1, out);

    const int smem_bytes = (4096 + 2048 * 3 + 64 + 16) * sizeof(float);  // 41,280 B
    cudaFuncSetAttribute(lrp_main_kernel,
                         cudaFuncAttributeMaxDynamicSharedMemorySize, smem_bytes);
    int grid = (PP + PPB - 1) / PPB;  // 1954
    lrp_main_kernel<<<grid, NTHREADS, smem_bytes>>>(
        nfeat, efeat_idx, n_row, n_col, n_val, e_col, e_val,
        p_row, p_val, weights, bias, bond_emb, out);
}